// round 1
// baseline (speedup 1.0000x reference)
#include <cuda_runtime.h>
#include <cuda_bf16.h>
#include <cstdint>

// out[m,u] = ||x_m||^2 - 2 * (x_m . w_u) + ||w_u||^2
// M = 524288, D = 64, U = 64. Cross term via bf16 mma.sync m16n8k16;
// x2 in fp32 from the same registers; w2 in fp32 from smem staging.

#define DEPTH 64
#define UNITS 64
#define WPAD  72   // padded bf16 row stride for w in smem (conflict-free B frags)

__device__ __forceinline__ uint32_t pack_bf16x2(float lo, float hi) {
    // cvt.rn.bf16x2.f32 d, a, b packs a into the HIGH half, b into the LOW half
    uint32_t r;
    asm("cvt.rn.bf16x2.f32 %0, %1, %2;" : "=r"(r) : "f"(hi), "f"(lo));
    return r;
}

__device__ __forceinline__ void mma_bf16(float c[4],
                                         uint32_t a0, uint32_t a1, uint32_t a2, uint32_t a3,
                                         uint32_t b0, uint32_t b1) {
    asm volatile(
        "mma.sync.aligned.m16n8k16.row.col.f32.bf16.bf16.f32 "
        "{%0,%1,%2,%3}, {%4,%5,%6,%7}, {%8,%9}, {%0,%1,%2,%3};"
        : "+f"(c[0]), "+f"(c[1]), "+f"(c[2]), "+f"(c[3])
        : "r"(a0), "r"(a1), "r"(a2), "r"(a3), "r"(b0), "r"(b1));
}

__global__ __launch_bounds__(256, 2) void sqdist_kernel(
    const float* __restrict__ x, const float* __restrict__ w,
    float* __restrict__ out)
{
    __shared__ __nv_bfloat16 w_s[UNITS * WPAD];  // [u][d], padded
    __shared__ float w2_s[UNITS];

    const int tid = threadIdx.x;

    // ---- Stage w -> smem (bf16) + w2 (fp32). thread t: row n=t/4, d-slice (t%4)*16..+15
    {
        const int n  = tid >> 2;
        const int dq = (tid & 3) * 16;
        const float* wp = w + n * DEPTH + dq;
        float psum = 0.f;
        #pragma unroll
        for (int i = 0; i < 4; i++) {
            float4 v = reinterpret_cast<const float4*>(wp)[i];
            psum += v.x * v.x + v.y * v.y + v.z * v.z + v.w * v.w;
            uint32_t* dst = reinterpret_cast<uint32_t*>(&w_s[n * WPAD + dq + i * 4]);
            dst[0] = pack_bf16x2(v.x, v.y);
            dst[1] = pack_bf16x2(v.z, v.w);
        }
        psum += __shfl_xor_sync(0xffffffffu, psum, 1);
        psum += __shfl_xor_sync(0xffffffffu, psum, 2);
        if ((tid & 3) == 0) w2_s[n] = psum;
    }
    __syncthreads();

    const int warp = tid >> 5;   // 0..7
    const int lane = tid & 31;
    const int g    = lane >> 2;  // groupID 0..7
    const int t4   = lane & 3;

    const long row0 = (long)blockIdx.x * 128 + warp * 16;
    const float* xp = x + row0 * DEPTH;

    // ---- Load A fragments (fp32) directly from global.
    // reg r: row = g + (r&1)*8, col = kb*16 + t4*2 + (r>>1)*8   -> float2 (2 consecutive d)
    float2 af[4][4];
    #pragma unroll
    for (int kb = 0; kb < 4; kb++) {
        const int kbase = kb * 16 + t4 * 2;
        #pragma unroll
        for (int r = 0; r < 4; r++) {
            const int row = g + (r & 1) * 8;
            const int col = kbase + (r >> 1) * 8;
            af[kb][r] = *reinterpret_cast<const float2*>(xp + row * DEPTH + col);
        }
    }

    // ---- x2 partial sums (exact fp32), reduce within lane-quad.
    float p_lo = 0.f, p_hi = 0.f;
    #pragma unroll
    for (int kb = 0; kb < 4; kb++) {
        p_lo += af[kb][0].x * af[kb][0].x + af[kb][0].y * af[kb][0].y;
        p_lo += af[kb][2].x * af[kb][2].x + af[kb][2].y * af[kb][2].y;
        p_hi += af[kb][1].x * af[kb][1].x + af[kb][1].y * af[kb][1].y;
        p_hi += af[kb][3].x * af[kb][3].x + af[kb][3].y * af[kb][3].y;
    }
    p_lo += __shfl_xor_sync(0xffffffffu, p_lo, 1);
    p_lo += __shfl_xor_sync(0xffffffffu, p_lo, 2);
    p_hi += __shfl_xor_sync(0xffffffffu, p_hi, 1);
    p_hi += __shfl_xor_sync(0xffffffffu, p_hi, 2);

    // ---- Convert A to bf16x2 fragments.
    uint32_t ab[4][4];
    #pragma unroll
    for (int kb = 0; kb < 4; kb++)
        #pragma unroll
        for (int r = 0; r < 4; r++)
            ab[kb][r] = pack_bf16x2(af[kb][r].x, af[kb][r].y);

    // ---- GEMM: 8 n-tiles x 4 k-blocks.
    float acc[8][4];
    #pragma unroll
    for (int nt = 0; nt < 8; nt++) {
        acc[nt][0] = acc[nt][1] = acc[nt][2] = acc[nt][3] = 0.f;
        const int n = nt * 8 + g;
        #pragma unroll
        for (int kb = 0; kb < 4; kb++) {
            const int k = kb * 16 + t4 * 2;
            uint32_t b0 = *reinterpret_cast<const uint32_t*>(&w_s[n * WPAD + k]);
            uint32_t b1 = *reinterpret_cast<const uint32_t*>(&w_s[n * WPAD + k + 8]);
            mma_bf16(acc[nt], ab[kb][0], ab[kb][1], ab[kb][2], ab[kb][3], b0, b1);
        }
    }

    // ---- Epilogue: out = x2 + w2 - 2*acc, float2 stores.
    #pragma unroll
    for (int nt = 0; nt < 8; nt++) {
        const int ucol = nt * 8 + t4 * 2;
        const float w2a = w2_s[ucol];
        const float w2b = w2_s[ucol + 1];
        float2 o0, o1;
        o0.x = p_lo + w2a - 2.f * acc[nt][0];
        o0.y = p_lo + w2b - 2.f * acc[nt][1];
        o1.x = p_hi + w2a - 2.f * acc[nt][2];
        o1.y = p_hi + w2b - 2.f * acc[nt][3];
        *reinterpret_cast<float2*>(out + (row0 + g) * UNITS + ucol)     = o0;
        *reinterpret_cast<float2*>(out + (row0 + g + 8) * UNITS + ucol) = o1;
    }
}

extern "C" void kernel_launch(void* const* d_in, const int* in_sizes, int n_in,
                              void* d_out, int out_size) {
    const float* x = (const float*)d_in[0];
    const float* w = (const float*)d_in[1];
    float* out = (float*)d_out;
    const int M = in_sizes[0] / DEPTH;      // 524288
    const int grid = M / 128;               // 4096 (M is a multiple of 128)
    sqdist_kernel<<<grid, 256>>>(x, w, out);
}